// round 4
// baseline (speedup 1.0000x reference)
#include <cuda_runtime.h>
#include <cuda_bf16.h>
#include <mma.h>
#include <cstdint>

using namespace nvcuda;

// Problem constants
#define BB 2
#define NN 2048
#define NP 2000
#define NREL 8192
#define BNR (BB*NREL)      // 16384
#define NODES (BB*NN)      // 4096
#define NF 128

// ---------------- scratch ---------------------------------------------------
__device__ float          g_pin_f[NODES*19];
__device__ __nv_bfloat16  g_pin_h[NODES*32];       // padded K=32
__device__ __nv_bfloat16  g_rin_h[BNR*64];         // padded K=64
__device__ __nv_bfloat16  g_pEnc[NODES*NF];
__device__ __nv_bfloat16  g_pEff[NODES*NF];
__device__ __nv_bfloat16  g_relE[BNR*NF];
__device__ float          g_agg[NODES*NF];
__device__ int            g_rr[BNR];
__device__ int            g_rs[BNR];
__device__ __nv_bfloat16  g_wbuf[1504*128];

// weight row offsets inside g_wbuf
#define WO_PE0 0
#define WO_PE1 32
#define WO_PE2 160
#define WO_RE0 288
#define WO_RE1 352
#define WO_RE2 480
#define WO_PP  608
#define WO_RP  864
#define WO_NP0 1248
#define WO_NP1 1376
#define W_TOTAL_ROWS 1504

// ---------------- helpers ---------------------------------------------------
__device__ __forceinline__ uint32_t pack_bf2(float a, float b) {
    __nv_bfloat162 h = __floats2bfloat162_rn(a, b);
    return *reinterpret_cast<uint32_t*>(&h);
}
__device__ __forceinline__ float2 unpack_bf2(uint32_t u) {
    __nv_bfloat162 h = *reinterpret_cast<__nv_bfloat162*>(&u);
    return make_float2(__bfloat162float(h.x), __bfloat162float(h.y));
}

// ---------------- weight conversion fp32 -> bf16 (zero-padded rows) ---------
struct WConvArgs {
    const float* src[10];
    int rowStart[10];
    int srcRows[10];
};
__global__ void convert_w(WConvArgs a, __nv_bfloat16* __restrict__ wbuf) {
    int row = blockIdx.x, col = threadIdx.x;
    int seg = 0;
#pragma unroll
    for (int i = 1; i < 10; i++) if (row >= a.rowStart[i]) seg = i;
    int r = row - a.rowStart[seg];
    float v = (r < a.srcRows[seg]) ? a.src[seg][r * 128 + col] : 0.f;
    wbuf[row * 128 + col] = __float2bfloat16(v);
}

// ---------------- index extraction (early-exit scan of one-hot rows) --------
__global__ void extract_idx(const float* __restrict__ Rr,
                            const float* __restrict__ Rs,
                            int* __restrict__ rr, int* __restrict__ rs) {
    int gw   = (blockIdx.x * blockDim.x + threadIdx.x) >> 5;
    int lane = threadIdx.x & 31;
    if (gw >= 2 * BNR) return;
    const float* src = (gw < BNR) ? Rr : Rs;
    int row = (gw < BNR) ? gw : gw - BNR;
    const float4* p = reinterpret_cast<const float4*>(src + (size_t)row * NN);
    int found = -1;
    for (int i = 0; i < NN / 128; i++) {
        float4 v = __ldcs(&p[i * 32 + lane]);
        int base = i * 128 + lane * 4;
        if (v.x != 0.f) found = base;
        if (v.y != 0.f) found = base + 1;
        if (v.z != 0.f) found = base + 2;
        if (v.w != 0.f) found = base + 3;
        if (__ballot_sync(0xffffffffu, found >= 0)) break;   // one-hot: done
    }
#pragma unroll
    for (int off = 16; off; off >>= 1)
        found = max(found, __shfl_xor_sync(0xffffffffu, found, off));
    if (lane == 0) {
        int b = row / NREL;
        ((gw < BNR) ? rr : rs)[row] = b * NN + found;
    }
}

// ---------------- build particle inputs -------------------------------------
__global__ void build_pin(const float* __restrict__ state,
                          const float* __restrict__ attrs,
                          const float* __restrict__ action,
                          const float* __restrict__ pden,
                          const float* __restrict__ phys,
                          float* __restrict__ pf,
                          __nv_bfloat16* __restrict__ ph) {
    int i = blockIdx.x * blockDim.x + threadIdx.x;
    if (i >= NODES) return;
    int b = i / NN, n = i - b * NN;
    float o[19];
    o[0] = attrs[i * 2 + 0];
    o[1] = attrs[i * 2 + 1];
    float s[4][3];
#pragma unroll
    for (int t = 0; t < 4; t++)
#pragma unroll
        for (int k = 0; k < 3; k++)
            s[t][k] = state[((size_t)(b * 4 + t) * NN + n) * 3 + k];
#pragma unroll
    for (int t = 0; t < 3; t++)
#pragma unroll
        for (int k = 0; k < 3; k++)
            o[2 + t * 3 + k] = s[t + 1][k] - s[t][k];
#pragma unroll
    for (int k = 0; k < 3; k++) o[11 + k] = s[3][k];
    bool isP = (n < NP);
    o[14] = isP ? phys[b] : 0.f;
#pragma unroll
    for (int k = 0; k < 3; k++) o[15 + k] = action[(size_t)i * 3 + k];
    o[18] = isP ? pden[b] : 0.f;
#pragma unroll
    for (int k = 0; k < 19; k++) pf[(size_t)i * 19 + k] = o[k];
#pragma unroll
    for (int k = 0; k < 19; k++) ph[(size_t)i * 32 + k] = __float2bfloat16(o[k]);
#pragma unroll
    for (int k = 19; k < 32; k++) ph[(size_t)i * 32 + k] = __float2bfloat16(0.f);
}

// ---------------- build relation inputs: element-parallel [BNR*64] ----------
__global__ void build_rin(const float* __restrict__ pf,
                          const float* __restrict__ attrs,
                          const float* __restrict__ pinst,
                          const int* __restrict__ rr, const int* __restrict__ rs,
                          __nv_bfloat16* __restrict__ rin) {
    int e = blockIdx.x * blockDim.x + threadIdx.x;
    if (e >= BNR * 64) return;
    int r = e >> 6, k = e & 63;
    int gr = rr[r], gs = rs[r];
    float v;
    if (k < 19)       v = pf[(size_t)gr * 19 + k];
    else if (k < 38)  v = pf[(size_t)gs * 19 + (k - 19)];
    else if (k < 40)  v = attrs[gr * 2 + (k - 38)];
    else if (k < 42)  v = attrs[gs * 2 + (k - 40)];
    else if (k == 42) {
        int b = r / NREL;
        int ir = gr & (NN - 1), is_ = gs & (NN - 1);
        float gd = 0.f;
#pragma unroll
        for (int j = 0; j < 8; j++) {
            float a = (ir < NP) ? pinst[((size_t)b * NP + ir) * 8 + j] : 0.f;
            float c = (is_ < NP) ? pinst[((size_t)b * NP + is_) * 8 + j] : 0.f;
            gd += fabsf(a - c);
        }
        v = gd;
    }
    else if (k < 55)  v = pf[(size_t)gr * 19 + 2 + (k - 43)]
                        - pf[(size_t)gs * 19 + 2 + (k - 43)];
    else if (k == 55) v = pf[(size_t)gr * 19 + 18] - pf[(size_t)gs * 19 + 18];
    else              v = 0.f;
    rin[e] = __float2bfloat16(v);
}

// =====================  fused 3-layer encoder MLP  ==========================
// BM=64 rows/block, weights resident in smem, activations never leave smem.
#define ENC_WROWS 320
#define ENC_W_BYTES (ENC_WROWS*136*2)              // 87040
#define ENC_BIAS_OFF ENC_W_BYTES
#define ENC_ACT_OFF (ENC_BIAS_OFF + 3*128*4)       // 88576
#define ENC_CS_OFF  (ENC_ACT_OFF + 64*136*2)       // 105984
#define ENC_SMEM    (ENC_CS_OFF + 64*132*4)        // 139776

struct EncSeg {
    const __nv_bfloat16* A; int K0;
    const __nv_bfloat16* W0; const __nv_bfloat16* W1; const __nv_bfloat16* W2;
    const float *b0, *b1, *b2;
    __nv_bfloat16* C; __nv_bfloat16* C2; float* aggz;
};

__global__ void __launch_bounds__(256) encmlp_k(EncSeg s1, EncSeg s2, int nb1) {
    extern __shared__ char smraw[];
    __nv_bfloat16* Wsm  = (__nv_bfloat16*)smraw;
    float* biasm        = (float*)(smraw + ENC_BIAS_OFF);
    __nv_bfloat16* Act  = (__nv_bfloat16*)(smraw + ENC_ACT_OFF);
    float* Cs           = (float*)(smraw + ENC_CS_OFF);
    int tid = threadIdx.x, wid = tid >> 5;
    int wm = wid & 3, wn = wid >> 2;
    bool first = blockIdx.x < nb1;
    EncSeg s = first ? s1 : s2;
    int rowBase = (first ? blockIdx.x : blockIdx.x - nb1) * 64;
    int K0 = s.K0;

    {
        int totRows = K0 + 256;
        for (int idx = tid; idx < totRows * 16; idx += 256) {
            int r = idx >> 4, c8 = (idx & 15) * 8;
            const __nv_bfloat16* src;
            if (r < K0)            src = s.W0 + (size_t)r * 128 + c8;
            else if (r < K0 + 128) src = s.W1 + (size_t)(r - K0) * 128 + c8;
            else                   src = s.W2 + (size_t)(r - K0 - 128) * 128 + c8;
            *(uint4*)&Wsm[r * 136 + c8] = *(const uint4*)src;
        }
        for (int i = tid; i < 128; i += 256) {
            biasm[i]       = s.b0[i];
            biasm[128 + i] = s.b1[i];
            biasm[256 + i] = s.b2[i];
        }
        int k8 = K0 / 8;
        for (int idx = tid; idx < 64 * k8; idx += 256) {
            int r = idx / k8, c8 = (idx % k8) * 8;
            *(uint4*)&Act[r * 136 + c8] =
                *(const uint4*)(s.A + (size_t)(rowBase + r) * K0 + c8);
        }
    }
    __syncthreads();

    for (int L = 0; L < 3; L++) {
        int KL = (L == 0) ? K0 : 128;
        const __nv_bfloat16* WL = Wsm + (size_t)((L == 0) ? 0 : K0 + (L - 1) * 128) * 136;
        wmma::fragment<wmma::accumulator, 16, 16, 16, float> acc[4];
#pragma unroll
        for (int nf = 0; nf < 4; nf++) wmma::fill_fragment(acc[nf], 0.f);
        for (int kc = 0; kc < KL / 16; kc++) {
            wmma::fragment<wmma::matrix_a, 16, 16, 16, __nv_bfloat16, wmma::row_major> af;
            wmma::load_matrix_sync(af, Act + (wm * 16) * 136 + kc * 16, 136);
#pragma unroll
            for (int nf = 0; nf < 4; nf++) {
                wmma::fragment<wmma::matrix_b, 16, 16, 16, __nv_bfloat16, wmma::row_major> bf;
                wmma::load_matrix_sync(bf, WL + (kc * 16) * 136 + wn * 64 + nf * 16, 136);
                wmma::mma_sync(acc[nf], af, bf, acc[nf]);
            }
        }
#pragma unroll
        for (int nf = 0; nf < 4; nf++)
            wmma::store_matrix_sync(Cs + (wm * 16) * 132 + wn * 64 + nf * 16,
                                    acc[nf], 132, wmma::mem_row_major);
        __syncthreads();
        const float* bL = biasm + L * 128;
#pragma unroll
        for (int it = 0; it < 8; it++) {
            int e = tid + it * 256, row = e >> 5, c4 = (e & 31) * 4;
            float4 v = *(float4*)&Cs[row * 132 + c4];
            float4 b = *(const float4*)&bL[c4];
            v.x = fmaxf(v.x + b.x, 0.f); v.y = fmaxf(v.y + b.y, 0.f);
            v.z = fmaxf(v.z + b.z, 0.f); v.w = fmaxf(v.w + b.w, 0.f);
            uint2 o; o.x = pack_bf2(v.x, v.y); o.y = pack_bf2(v.z, v.w);
            if (L < 2) {
                *(uint2*)&Act[row * 136 + c4] = o;
            } else {
                size_t go = (size_t)(rowBase + row) * 128 + c4;
                *(uint2*)&s.C[go] = o;
                if (s.C2)   *(uint2*)&s.C2[go] = o;
                if (s.aggz) *(float4*)&s.aggz[go] = make_float4(0.f, 0.f, 0.f, 0.f);
            }
        }
        __syncthreads();
    }
}

// =====================  relation propagator  ================================
#define RP_CS_OFF   (384*136*2)                    // 104448
#define RP_AB_OFF   (RP_CS_OFF + 64*132*4)         // 138240
#define RP_IDX_OFF  (RP_AB_OFF + 8*16*24*2)        // 144384
#define RP_BIAS_OFF (RP_IDX_OFF + 512)             // 144896
#define RP_SMEM     (RP_BIAS_OFF + 512)            // 145408

__global__ void __launch_bounds__(256) relprop_k(
    const __nv_bfloat16* __restrict__ relE, const __nv_bfloat16* __restrict__ pEff,
    const __nv_bfloat16* __restrict__ W, const float* __restrict__ bias,
    float* __restrict__ agg, const int* __restrict__ rr, const int* __restrict__ rs)
{
    extern __shared__ char smraw[];
    __nv_bfloat16* Wsm = (__nv_bfloat16*)smraw;
    float* Cs          = (float*)(smraw + RP_CS_OFF);
    __nv_bfloat16* Ab  = (__nv_bfloat16*)(smraw + RP_AB_OFF);
    int*   idxs        = (int*)(smraw + RP_IDX_OFF);
    float* biasm       = (float*)(smraw + RP_BIAS_OFF);
    int tid = threadIdx.x, wid = tid >> 5, lane = tid & 31;
    int wm = wid & 3, wn = wid >> 2;
    int rowBase = blockIdx.x * 64;

    for (int idx = tid; idx < 384 * 16; idx += 256) {
        int r = idx >> 4, c8 = (idx & 15) * 8;
        *(uint4*)&Wsm[r * 136 + c8] = *(const uint4*)(W + (size_t)r * 128 + c8);
    }
    if (tid < 64)            idxs[tid]      = rr[rowBase + tid];
    else if (tid < 128)      idxs[tid]      = rs[rowBase + tid - 64];
    if (tid < 128) biasm[tid] = bias[tid];
    __syncthreads();

    wmma::fragment<wmma::accumulator, 16, 16, 16, float> acc[4];
#pragma unroll
    for (int nf = 0; nf < 4; nf++) wmma::fill_fragment(acc[nf], 0.f);

    __nv_bfloat16* ab = Ab + wid * (16 * 24);
    int r  = lane >> 1;
    int h8 = (lane & 1) * 8;
    int lrow = wm * 16 + r;

    for (int kc = 0; kc < 24; kc++) {
        int seg = kc >> 3, col = (kc & 7) * 16 + h8;
        const __nv_bfloat16* src;
        if (seg == 0)      src = relE + (size_t)(rowBase + lrow) * 128 + col;
        else if (seg == 1) src = pEff + (size_t)idxs[lrow] * 128 + col;
        else               src = pEff + (size_t)idxs[64 + lrow] * 128 + col;
        *(uint4*)&ab[r * 24 + h8] = *(const uint4*)src;
        __syncwarp();
        wmma::fragment<wmma::matrix_a, 16, 16, 16, __nv_bfloat16, wmma::row_major> af;
        wmma::load_matrix_sync(af, ab, 24);
        __syncwarp();
#pragma unroll
        for (int nf = 0; nf < 4; nf++) {
            wmma::fragment<wmma::matrix_b, 16, 16, 16, __nv_bfloat16, wmma::row_major> bf;
            wmma::load_matrix_sync(bf, Wsm + (kc * 16) * 136 + wn * 64 + nf * 16, 136);
            wmma::mma_sync(acc[nf], af, bf, acc[nf]);
        }
    }
#pragma unroll
    for (int nf = 0; nf < 4; nf++)
        wmma::store_matrix_sync(Cs + (wm * 16) * 132 + wn * 64 + nf * 16,
                                acc[nf], 132, wmma::mem_row_major);
    __syncthreads();
#pragma unroll
    for (int it = 0; it < 8; it++) {
        int e = tid + it * 256, row = e >> 5, c4 = (e & 31) * 4;
        float4 v = *(float4*)&Cs[row * 132 + c4];
        float4 b = *(const float4*)&biasm[c4];
        float* dst = agg + (size_t)idxs[row] * 128 + c4;
        atomicAdd(dst + 0, fmaxf(v.x + b.x, 0.f));
        atomicAdd(dst + 1, fmaxf(v.y + b.y, 0.f));
        atomicAdd(dst + 2, fmaxf(v.z + b.z, 0.f));
        atomicAdd(dst + 3, fmaxf(v.w + b.w, 0.f));
    }
}

// =====================  particle propagator  ================================
#define PP_CS_OFF   (256*136*2)                    // 69632
#define PP_AB_OFF   (PP_CS_OFF + 32*132*4)         // 86528
#define PP_BIAS_OFF (PP_AB_OFF + 8*16*24*2)        // 92672
#define PP_SMEM     (PP_BIAS_OFF + 512)            // 93184

__global__ void __launch_bounds__(256) partprop_k(
    const __nv_bfloat16* __restrict__ pEnc, float* __restrict__ agg,
    const __nv_bfloat16* __restrict__ W, const float* __restrict__ bias,
    __nv_bfloat16* __restrict__ pEff)
{
    extern __shared__ char smraw[];
    __nv_bfloat16* Wsm = (__nv_bfloat16*)smraw;
    float* Cs          = (float*)(smraw + PP_CS_OFF);
    __nv_bfloat16* Ab  = (__nv_bfloat16*)(smraw + PP_AB_OFF);
    float* biasm       = (float*)(smraw + PP_BIAS_OFF);
    int tid = threadIdx.x, wid = tid >> 5, lane = tid & 31;
    int wm = wid & 1, wn = wid >> 1;
    int rowBase = blockIdx.x * 32;

    for (int idx = tid; idx < 256 * 16; idx += 256) {
        int r = idx >> 4, c8 = (idx & 15) * 8;
        *(uint4*)&Wsm[r * 136 + c8] = *(const uint4*)(W + (size_t)r * 128 + c8);
    }
    if (tid < 128) biasm[tid] = bias[tid];
    __syncthreads();

    wmma::fragment<wmma::accumulator, 16, 16, 16, float> acc[2];
#pragma unroll
    for (int nf = 0; nf < 2; nf++) wmma::fill_fragment(acc[nf], 0.f);

    __nv_bfloat16* ab = Ab + wid * (16 * 24);
    int r  = lane >> 1;
    int h8 = (lane & 1) * 8;
    int g  = rowBase + wm * 16 + r;

    for (int kc = 0; kc < 16; kc++) {
        int col = (kc & 7) * 16 + h8;
        uint4 v;
        if (kc < 8) {
            v = *(const uint4*)(pEnc + (size_t)g * 128 + col);
        } else {
            const float* ap = agg + (size_t)g * 128 + col;
            float4 f0 = *(const float4*)ap;
            float4 f1 = *(const float4*)(ap + 4);
            v.x = pack_bf2(f0.x, f0.y); v.y = pack_bf2(f0.z, f0.w);
            v.z = pack_bf2(f1.x, f1.y); v.w = pack_bf2(f1.z, f1.w);
        }
        *(uint4*)&ab[r * 24 + h8] = v;
        __syncwarp();
        wmma::fragment<wmma::matrix_a, 16, 16, 16, __nv_bfloat16, wmma::row_major> af;
        wmma::load_matrix_sync(af, ab, 24);
        __syncwarp();
#pragma unroll
        for (int nf = 0; nf < 2; nf++) {
            wmma::fragment<wmma::matrix_b, 16, 16, 16, __nv_bfloat16, wmma::row_major> bf;
            wmma::load_matrix_sync(bf, Wsm + (kc * 16) * 136 + wn * 32 + nf * 16, 136);
            wmma::mma_sync(acc[nf], af, bf, acc[nf]);
        }
    }
#pragma unroll
    for (int nf = 0; nf < 2; nf++)
        wmma::store_matrix_sync(Cs + (wm * 16) * 132 + wn * 32 + nf * 16,
                                acc[nf], 132, wmma::mem_row_major);
    __syncthreads();
#pragma unroll
    for (int it = 0; it < 4; it++) {
        int e = tid + it * 256, row = e >> 5, c4 = (e & 31) * 4;
        size_t go = (size_t)(rowBase + row) * 128 + c4;
        float4 v = *(float4*)&Cs[row * 132 + c4];
        float4 b = *(const float4*)&biasm[c4];
        uint2 rv = *(const uint2*)&pEff[go];
        float2 r0 = unpack_bf2(rv.x), r1 = unpack_bf2(rv.y);
        v.x = fmaxf(v.x + b.x + r0.x, 0.f);
        v.y = fmaxf(v.y + b.y + r0.y, 0.f);
        v.z = fmaxf(v.z + b.z + r1.x, 0.f);
        v.w = fmaxf(v.w + b.w + r1.y, 0.f);
        uint2 o; o.x = pack_bf2(v.x, v.y); o.y = pack_bf2(v.z, v.w);
        *(uint2*)&pEff[go] = o;
        *(float4*)&agg[go] = make_float4(0.f, 0.f, 0.f, 0.f);
    }
}

// =====================  fused head: np0 + np1 + np2 + clamp + add ===========
#define HD_BIAS_OFF (256*136*2)                    // 69632
#define HD_W2_OFF   (HD_BIAS_OFF + 2*128*4)        // 70656
#define HD_B2_OFF   (HD_W2_OFF + 384*4)            // 72192
#define HD_ACT_OFF  (HD_B2_OFF + 16)               // 72208
#define HD_CS_OFF   (HD_ACT_OFF + 64*136*2)        // 89616
#define HD_SMEM     (HD_CS_OFF + 64*132*4)         // 123408

__global__ void __launch_bounds__(256) head_k(
    const __nv_bfloat16* __restrict__ pEff,
    const __nv_bfloat16* __restrict__ W0, const __nv_bfloat16* __restrict__ W1,
    const float* __restrict__ b0, const float* __restrict__ b1,
    const float* __restrict__ W2, const float* __restrict__ b2,
    const float* __restrict__ state, float* __restrict__ out)
{
    extern __shared__ char smraw[];
    __nv_bfloat16* Wsm  = (__nv_bfloat16*)smraw;
    float* biasm        = (float*)(smraw + HD_BIAS_OFF);
    float* W2s          = (float*)(smraw + HD_W2_OFF);
    float* b2s          = (float*)(smraw + HD_B2_OFF);
    __nv_bfloat16* Act  = (__nv_bfloat16*)(smraw + HD_ACT_OFF);
    float* Cs           = (float*)(smraw + HD_CS_OFF);
    int tid = threadIdx.x, wid = tid >> 5, lane = tid & 31;
    int wm = wid & 3, wn = wid >> 2;
    int rowBase = blockIdx.x * 64;

    for (int idx = tid; idx < 256 * 16; idx += 256) {
        int r = idx >> 4, c8 = (idx & 15) * 8;
        const __nv_bfloat16* src = (r < 128) ? W0 + (size_t)r * 128 + c8
                                             : W1 + (size_t)(r - 128) * 128 + c8;
        *(uint4*)&Wsm[r * 136 + c8] = *(const uint4*)src;
    }
    for (int i = tid; i < 128; i += 256) { biasm[i] = b0[i]; biasm[128 + i] = b1[i]; }
    for (int i = tid; i < 384; i += 256) W2s[i] = W2[i];
    if (tid < 3) b2s[tid] = b2[tid];
    for (int idx = tid; idx < 64 * 16; idx += 256) {
        int r = idx >> 4, c8 = (idx & 15) * 8;
        *(uint4*)&Act[r * 136 + c8] =
            *(const uint4*)(pEff + (size_t)(rowBase + r) * 128 + c8);
    }
    __syncthreads();

    for (int L = 0; L < 2; L++) {
        const __nv_bfloat16* WL = Wsm + (size_t)L * 128 * 136;
        wmma::fragment<wmma::accumulator, 16, 16, 16, float> acc[4];
#pragma unroll
        for (int nf = 0; nf < 4; nf++) wmma::fill_fragment(acc[nf], 0.f);
#pragma unroll
        for (int kc = 0; kc < 8; kc++) {
            wmma::fragment<wmma::matrix_a, 16, 16, 16, __nv_bfloat16, wmma::row_major> af;
            wmma::load_matrix_sync(af, Act + (wm * 16) * 136 + kc * 16, 136);
#pragma unroll
            for (int nf = 0; nf < 4; nf++) {
                wmma::fragment<wmma::matrix_b, 16, 16, 16, __nv_bfloat16, wmma::row_major> bf;
                wmma::load_matrix_sync(bf, WL + (kc * 16) * 136 + wn * 64 + nf * 16, 136);
                wmma::mma_sync(acc[nf], af, bf, acc[nf]);
            }
        }
#pragma unroll
        for (int nf = 0; nf < 4; nf++)
            wmma::store_matrix_sync(Cs + (wm * 16) * 132 + wn * 64 + nf * 16,
                                    acc[nf], 132, wmma::mem_row_major);
        __syncthreads();
        const float* bL = biasm + L * 128;
#pragma unroll
        for (int it = 0; it < 8; it++) {
            int e = tid + it * 256, row = e >> 5, c4 = (e & 31) * 4;
            float4 v = *(float4*)&Cs[row * 132 + c4];
            float4 b = *(const float4*)&bL[c4];
            uint2 o;
            o.x = pack_bf2(fmaxf(v.x + b.x, 0.f), fmaxf(v.y + b.y, 0.f));
            o.y = pack_bf2(fmaxf(v.z + b.z, 0.f), fmaxf(v.w + b.w, 0.f));
            *(uint2*)&Act[row * 136 + c4] = o;
        }
        __syncthreads();
    }

    // final 128->3, clamp, add last position
#pragma unroll
    for (int i = 0; i < 8; i++) {
        int row = wid * 8 + i;
        int grow = rowBase + row;
        int b = grow >> 11, n = grow & (NN - 1);
        float hv[4];
#pragma unroll
        for (int j = 0; j < 4; j++)
            hv[j] = __bfloat162float(Act[row * 136 + lane + 32 * j]);
#pragma unroll
        for (int k = 0; k < 3; k++) {
            float sacc = 0.f;
#pragma unroll
            for (int j = 0; j < 4; j++)
                sacc += hv[j] * W2s[(lane + 32 * j) * 3 + k];
#pragma unroll
            for (int off = 16; off; off >>= 1)
                sacc += __shfl_xor_sync(0xffffffffu, sacc, off);
            if (lane == 0 && n < NP) {
                float m = fminf(fmaxf(sacc + b2s[k], -100.f), 100.f);
                out[((size_t)b * NP + n) * 3 + k] =
                    state[((size_t)(b * 4 + 3) * NN + n) * 3 + k] + m;
            }
        }
    }
}

// ---------------------------------------------------------------------------
extern "C" void kernel_launch(void* const* d_in, const int* in_sizes, int n_in,
                              void* d_out, int out_size) {
    const float* state  = (const float*)d_in[0];
    const float* attrs  = (const float*)d_in[1];
    const float* Rr     = (const float*)d_in[2];
    const float* Rs     = (const float*)d_in[3];
    const float* pinst  = (const float*)d_in[4];
    const float* action = (const float*)d_in[5];
    const float* pden   = (const float*)d_in[6];
    const float* phys   = (const float*)d_in[7];
    const float* pe_W0 = (const float*)d_in[8],  *pe_b0 = (const float*)d_in[9];
    const float* pe_W1 = (const float*)d_in[10], *pe_b1 = (const float*)d_in[11];
    const float* pe_W2 = (const float*)d_in[12], *pe_b2 = (const float*)d_in[13];
    const float* re_W0 = (const float*)d_in[14], *re_b0 = (const float*)d_in[15];
    const float* re_W1 = (const float*)d_in[16], *re_b1 = (const float*)d_in[17];
    const float* re_W2 = (const float*)d_in[18], *re_b2 = (const float*)d_in[19];
    const float* pp_W  = (const float*)d_in[20], *pp_b  = (const float*)d_in[21];
    const float* rp_W  = (const float*)d_in[22], *rp_b  = (const float*)d_in[23];
    const float* np_W0 = (const float*)d_in[24], *np_b0 = (const float*)d_in[25];
    const float* np_W1 = (const float*)d_in[26], *np_b1 = (const float*)d_in[27];
    const float* np_W2 = (const float*)d_in[28], *np_b2 = (const float*)d_in[29];
    float* out = (float*)d_out;

    float *pin_f, *agg;
    __nv_bfloat16 *pin_h, *rin_h, *pEnc, *pEff, *relE, *wbuf;
    int *rr, *rs;
    cudaGetSymbolAddress((void**)&pin_f, g_pin_f);
    cudaGetSymbolAddress((void**)&pin_h, g_pin_h);
    cudaGetSymbolAddress((void**)&rin_h, g_rin_h);
    cudaGetSymbolAddress((void**)&pEnc,  g_pEnc);
    cudaGetSymbolAddress((void**)&pEff,  g_pEff);
    cudaGetSymbolAddress((void**)&relE,  g_relE);
    cudaGetSymbolAddress((void**)&agg,   g_agg);
    cudaGetSymbolAddress((void**)&rr,    g_rr);
    cudaGetSymbolAddress((void**)&rs,    g_rs);
    cudaGetSymbolAddress((void**)&wbuf,  g_wbuf);

    cudaFuncSetAttribute(encmlp_k,  cudaFuncAttributeMaxDynamicSharedMemorySize, ENC_SMEM);
    cudaFuncSetAttribute(relprop_k, cudaFuncAttributeMaxDynamicSharedMemorySize, RP_SMEM);
    cudaFuncSetAttribute(partprop_k,cudaFuncAttributeMaxDynamicSharedMemorySize, PP_SMEM);
    cudaFuncSetAttribute(head_k,    cudaFuncAttributeMaxDynamicSharedMemorySize, HD_SMEM);

    // 0) weights -> bf16
    WConvArgs wa;
    const float* srcs[10] = {pe_W0, pe_W1, pe_W2, re_W0, re_W1, re_W2,
                             pp_W, rp_W, np_W0, np_W1};
    const int starts[10]  = {WO_PE0, WO_PE1, WO_PE2, WO_RE0, WO_RE1, WO_RE2,
                             WO_PP, WO_RP, WO_NP0, WO_NP1};
    const int srows[10]   = {19, 128, 128, 56, 128, 128, 256, 384, 128, 128};
    for (int i = 0; i < 10; i++) {
        wa.src[i] = srcs[i]; wa.rowStart[i] = starts[i]; wa.srcRows[i] = srows[i];
    }
    convert_w<<<W_TOTAL_ROWS, 128>>>(wa, wbuf);

    // 1) edge indices
    extract_idx<<<(2 * BNR * 32 + 255) / 256, 256>>>(Rr, Rs, rr, rs);

    // 2) feature assembly
    build_pin<<<(NODES + 255) / 256, 256>>>(state, attrs, action, pden, phys,
                                            pin_f, pin_h);
    build_rin<<<(BNR * 64) / 256, 256>>>(pin_f, attrs, pinst, rr, rs, rin_h);

    // 3) fused 3-layer encoders (particle segment also dups pEff + zeroes agg)
    EncSeg sp, sr;
    sp.A = pin_h; sp.K0 = 32;
    sp.W0 = wbuf + WO_PE0 * 128; sp.W1 = wbuf + WO_PE1 * 128; sp.W2 = wbuf + WO_PE2 * 128;
    sp.b0 = pe_b0; sp.b1 = pe_b1; sp.b2 = pe_b2;
    sp.C = pEnc; sp.C2 = pEff; sp.aggz = agg;
    sr.A = rin_h; sr.K0 = 64;
    sr.W0 = wbuf + WO_RE0 * 128; sr.W1 = wbuf + WO_RE1 * 128; sr.W2 = wbuf + WO_RE2 * 128;
    sr.b0 = re_b0; sr.b1 = re_b1; sr.b2 = re_b2;
    sr.C = relE; sr.C2 = nullptr; sr.aggz = nullptr;
    encmlp_k<<<NODES / 64 + BNR / 64, 256, ENC_SMEM>>>(sp, sr, NODES / 64);

    // 4) propagation: 3 steps
    for (int step = 0; step < 3; step++) {
        relprop_k<<<BNR / 64, 256, RP_SMEM>>>(relE, pEff, wbuf + WO_RP * 128,
                                              rp_b, agg, rr, rs);
        partprop_k<<<NODES / 32, 256, PP_SMEM>>>(pEnc, agg, wbuf + WO_PP * 128,
                                                 pp_b, pEff);
    }

    // 5) fused head
    head_k<<<NODES / 64, 256, HD_SMEM>>>(pEff, wbuf + WO_NP0 * 128,
                                         wbuf + WO_NP1 * 128, np_b0, np_b1,
                                         np_W2, np_b2, state, out);
}

// round 5
// speedup vs baseline: 1.3087x; 1.3087x over previous
#include <cuda_runtime.h>
#include <cuda_bf16.h>
#include <mma.h>
#include <cstdint>

using namespace nvcuda;

// Problem constants
#define BB 2
#define NN 2048
#define NP 2000
#define NREL 8192
#define BNR (BB*NREL)      // 16384
#define NODES (BB*NN)      // 4096
#define NF 128

// ---------------- scratch ---------------------------------------------------
__device__ float          g_pin_f[NODES*19];
__device__ __nv_bfloat16  g_pin_h[NODES*32];       // padded K=32
__device__ __nv_bfloat16  g_rin_h[BNR*64];         // padded K=64
__device__ __nv_bfloat16  g_pEnc[NODES*NF];
__device__ __nv_bfloat16  g_pEff[NODES*NF];
__device__ __nv_bfloat16  g_relE[BNR*NF];
__device__ __nv_bfloat16  g_aggH[NODES*NF];        // bf16 aggregation buffer
__device__ int            g_rr[BNR];
__device__ int            g_rs[BNR];
__device__ __nv_bfloat16  g_wbuf[1504*128];

// weight row offsets inside g_wbuf
#define WO_PE0 0
#define WO_PE1 32
#define WO_PE2 160
#define WO_RE0 288
#define WO_RE1 352
#define WO_RE2 480
#define WO_PP  608
#define WO_RP  864
#define WO_NP0 1248
#define WO_NP1 1376
#define W_TOTAL_ROWS 1504

// ---------------- helpers ---------------------------------------------------
__device__ __forceinline__ uint32_t pack_bf2(float a, float b) {
    __nv_bfloat162 h = __floats2bfloat162_rn(a, b);
    return *reinterpret_cast<uint32_t*>(&h);
}
__device__ __forceinline__ float2 unpack_bf2(uint32_t u) {
    __nv_bfloat162 h = *reinterpret_cast<__nv_bfloat162*>(&u);
    return make_float2(__bfloat162float(h.x), __bfloat162float(h.y));
}
__device__ __forceinline__ void cpa16(uint32_t d, const void* s) {
    asm volatile("cp.async.cg.shared.global [%0], [%1], 16;" :: "r"(d), "l"(s));
}
__device__ __forceinline__ void cpa8(uint32_t d, const void* s) {
    asm volatile("cp.async.ca.shared.global [%0], [%1], 8;" :: "r"(d), "l"(s));
}
__device__ __forceinline__ void cpa4(uint32_t d, const void* s) {
    asm volatile("cp.async.ca.shared.global [%0], [%1], 4;" :: "r"(d), "l"(s));
}
__device__ __forceinline__ void cp_commit() {
    asm volatile("cp.async.commit_group;" ::: "memory");
}
__device__ __forceinline__ void cp_wait1() {
    asm volatile("cp.async.wait_group 1;" ::: "memory");
}
__device__ __forceinline__ void cp_wait0() {
    asm volatile("cp.async.wait_group 0;" ::: "memory");
}

// ---------------- weight conversion fp32 -> bf16 (zero-padded rows) ---------
struct WConvArgs {
    const float* src[10];
    int rowStart[10];
    int srcRows[10];
};
__global__ void convert_w(WConvArgs a, __nv_bfloat16* __restrict__ wbuf) {
    int row = blockIdx.x, col = threadIdx.x;
    int seg = 0;
#pragma unroll
    for (int i = 1; i < 10; i++) if (row >= a.rowStart[i]) seg = i;
    int r = row - a.rowStart[seg];
    float v = (r < a.srcRows[seg]) ? a.src[seg][r * 128 + col] : 0.f;
    wbuf[row * 128 + col] = __float2bfloat16(v);
}

// ---------------- index extraction (early-exit scan of one-hot rows) --------
__global__ void extract_idx(const float* __restrict__ Rr,
                            const float* __restrict__ Rs,
                            int* __restrict__ rr, int* __restrict__ rs) {
    int gw   = (blockIdx.x * blockDim.x + threadIdx.x) >> 5;
    int lane = threadIdx.x & 31;
    if (gw >= 2 * BNR) return;
    const float* src = (gw < BNR) ? Rr : Rs;
    int row = (gw < BNR) ? gw : gw - BNR;
    const float4* p = reinterpret_cast<const float4*>(src + (size_t)row * NN);
    int found = -1;
    for (int i = 0; i < NN / 128; i++) {
        float4 v = __ldcs(&p[i * 32 + lane]);
        int base = i * 128 + lane * 4;
        if (v.x != 0.f) found = base;
        if (v.y != 0.f) found = base + 1;
        if (v.z != 0.f) found = base + 2;
        if (v.w != 0.f) found = base + 3;
        if (__ballot_sync(0xffffffffu, found >= 0)) break;   // one-hot: done
    }
#pragma unroll
    for (int off = 16; off; off >>= 1)
        found = max(found, __shfl_xor_sync(0xffffffffu, found, off));
    if (lane == 0) {
        int b = row / NREL;
        ((gw < BNR) ? rr : rs)[row] = b * NN + found;
    }
}

// ---------------- build particle inputs -------------------------------------
__global__ void build_pin(const float* __restrict__ state,
                          const float* __restrict__ attrs,
                          const float* __restrict__ action,
                          const float* __restrict__ pden,
                          const float* __restrict__ phys,
                          float* __restrict__ pf,
                          __nv_bfloat16* __restrict__ ph) {
    int i = blockIdx.x * blockDim.x + threadIdx.x;
    if (i >= NODES) return;
    int b = i / NN, n = i - b * NN;
    float o[19];
    o[0] = attrs[i * 2 + 0];
    o[1] = attrs[i * 2 + 1];
    float s[4][3];
#pragma unroll
    for (int t = 0; t < 4; t++)
#pragma unroll
        for (int k = 0; k < 3; k++)
            s[t][k] = state[((size_t)(b * 4 + t) * NN + n) * 3 + k];
#pragma unroll
    for (int t = 0; t < 3; t++)
#pragma unroll
        for (int k = 0; k < 3; k++)
            o[2 + t * 3 + k] = s[t + 1][k] - s[t][k];
#pragma unroll
    for (int k = 0; k < 3; k++) o[11 + k] = s[3][k];
    bool isP = (n < NP);
    o[14] = isP ? phys[b] : 0.f;
#pragma unroll
    for (int k = 0; k < 3; k++) o[15 + k] = action[(size_t)i * 3 + k];
    o[18] = isP ? pden[b] : 0.f;
#pragma unroll
    for (int k = 0; k < 19; k++) pf[(size_t)i * 19 + k] = o[k];
#pragma unroll
    for (int k = 0; k < 19; k++) ph[(size_t)i * 32 + k] = __float2bfloat16(o[k]);
#pragma unroll
    for (int k = 19; k < 32; k++) ph[(size_t)i * 32 + k] = __float2bfloat16(0.f);
}

// ---------------- build relation inputs: element-parallel [BNR*64] ----------
__global__ void build_rin(const float* __restrict__ pf,
                          const float* __restrict__ attrs,
                          const float* __restrict__ pinst,
                          const int* __restrict__ rr, const int* __restrict__ rs,
                          __nv_bfloat16* __restrict__ rin) {
    int e = blockIdx.x * blockDim.x + threadIdx.x;
    if (e >= BNR * 64) return;
    int r = e >> 6, k = e & 63;
    int gr = rr[r], gs = rs[r];
    float v;
    if (k < 19)       v = pf[(size_t)gr * 19 + k];
    else if (k < 38)  v = pf[(size_t)gs * 19 + (k - 19)];
    else if (k < 40)  v = attrs[gr * 2 + (k - 38)];
    else if (k < 42)  v = attrs[gs * 2 + (k - 40)];
    else if (k == 42) {
        int b = r / NREL;
        int ir = gr & (NN - 1), is_ = gs & (NN - 1);
        float gd = 0.f;
#pragma unroll
        for (int j = 0; j < 8; j++) {
            float a = (ir < NP) ? pinst[((size_t)b * NP + ir) * 8 + j] : 0.f;
            float c = (is_ < NP) ? pinst[((size_t)b * NP + is_) * 8 + j] : 0.f;
            gd += fabsf(a - c);
        }
        v = gd;
    }
    else if (k < 55)  v = pf[(size_t)gr * 19 + 2 + (k - 43)]
                        - pf[(size_t)gs * 19 + 2 + (k - 43)];
    else if (k == 55) v = pf[(size_t)gr * 19 + 18] - pf[(size_t)gs * 19 + 18];
    else              v = 0.f;
    rin[e] = __float2bfloat16(v);
}

// =====================  fused 3-layer encoder MLP  ==========================
// BM=64 rows/block, weights resident in smem, activations never leave smem.
#define ENC_WROWS 320
#define ENC_W_BYTES (ENC_WROWS*136*2)              // 87040
#define ENC_BIAS_OFF ENC_W_BYTES
#define ENC_ACT_OFF (ENC_BIAS_OFF + 3*128*4)       // 88576
#define ENC_CS_OFF  (ENC_ACT_OFF + 64*136*2)       // 105984
#define ENC_SMEM    (ENC_CS_OFF + 64*132*4)        // 139776

struct EncSeg {
    const __nv_bfloat16* A; int K0;
    const __nv_bfloat16* W0; const __nv_bfloat16* W1; const __nv_bfloat16* W2;
    const float *b0, *b1, *b2;
    __nv_bfloat16* C; __nv_bfloat16* C2; __nv_bfloat16* aggz;
};

__global__ void __launch_bounds__(256) encmlp_k(EncSeg s1, EncSeg s2, int nb1) {
    extern __shared__ char smraw[];
    __nv_bfloat16* Wsm  = (__nv_bfloat16*)smraw;
    float* biasm        = (float*)(smraw + ENC_BIAS_OFF);
    __nv_bfloat16* Act  = (__nv_bfloat16*)(smraw + ENC_ACT_OFF);
    float* Cs           = (float*)(smraw + ENC_CS_OFF);
    int tid = threadIdx.x, wid = tid >> 5;
    int wm = wid & 3, wn = wid >> 2;
    bool first = blockIdx.x < nb1;
    EncSeg s = first ? s1 : s2;
    int rowBase = (first ? blockIdx.x : blockIdx.x - nb1) * 64;
    int K0 = s.K0;

    {
        int totRows = K0 + 256;
        for (int idx = tid; idx < totRows * 16; idx += 256) {
            int r = idx >> 4, c8 = (idx & 15) * 8;
            const __nv_bfloat16* src;
            if (r < K0)            src = s.W0 + (size_t)r * 128 + c8;
            else if (r < K0 + 128) src = s.W1 + (size_t)(r - K0) * 128 + c8;
            else                   src = s.W2 + (size_t)(r - K0 - 128) * 128 + c8;
            *(uint4*)&Wsm[r * 136 + c8] = *(const uint4*)src;
        }
        for (int i = tid; i < 128; i += 256) {
            biasm[i]       = s.b0[i];
            biasm[128 + i] = s.b1[i];
            biasm[256 + i] = s.b2[i];
        }
        int k8 = K0 / 8;
        for (int idx = tid; idx < 64 * k8; idx += 256) {
            int r = idx / k8, c8 = (idx % k8) * 8;
            *(uint4*)&Act[r * 136 + c8] =
                *(const uint4*)(s.A + (size_t)(rowBase + r) * K0 + c8);
        }
    }
    __syncthreads();

    for (int L = 0; L < 3; L++) {
        int KL = (L == 0) ? K0 : 128;
        const __nv_bfloat16* WL = Wsm + (size_t)((L == 0) ? 0 : K0 + (L - 1) * 128) * 136;
        wmma::fragment<wmma::accumulator, 16, 16, 16, float> acc[4];
#pragma unroll
        for (int nf = 0; nf < 4; nf++) wmma::fill_fragment(acc[nf], 0.f);
        for (int kc = 0; kc < KL / 16; kc++) {
            wmma::fragment<wmma::matrix_a, 16, 16, 16, __nv_bfloat16, wmma::row_major> af;
            wmma::load_matrix_sync(af, Act + (wm * 16) * 136 + kc * 16, 136);
#pragma unroll
            for (int nf = 0; nf < 4; nf++) {
                wmma::fragment<wmma::matrix_b, 16, 16, 16, __nv_bfloat16, wmma::row_major> bf;
                wmma::load_matrix_sync(bf, WL + (kc * 16) * 136 + wn * 64 + nf * 16, 136);
                wmma::mma_sync(acc[nf], af, bf, acc[nf]);
            }
        }
#pragma unroll
        for (int nf = 0; nf < 4; nf++)
            wmma::store_matrix_sync(Cs + (wm * 16) * 132 + wn * 64 + nf * 16,
                                    acc[nf], 132, wmma::mem_row_major);
        __syncthreads();
        const float* bL = biasm + L * 128;
#pragma unroll
        for (int it = 0; it < 8; it++) {
            int e = tid + it * 256, row = e >> 5, c4 = (e & 31) * 4;
            float4 v = *(float4*)&Cs[row * 132 + c4];
            float4 b = *(const float4*)&bL[c4];
            v.x = fmaxf(v.x + b.x, 0.f); v.y = fmaxf(v.y + b.y, 0.f);
            v.z = fmaxf(v.z + b.z, 0.f); v.w = fmaxf(v.w + b.w, 0.f);
            uint2 o; o.x = pack_bf2(v.x, v.y); o.y = pack_bf2(v.z, v.w);
            if (L < 2) {
                *(uint2*)&Act[row * 136 + c4] = o;
            } else {
                size_t go = (size_t)(rowBase + row) * 128 + c4;
                *(uint2*)&s.C[go] = o;
                if (s.C2)   *(uint2*)&s.C2[go] = o;
                if (s.aggz) *(uint2*)&s.aggz[go] = make_uint2(0u, 0u);
            }
        }
        __syncthreads();
    }
}

// =============  pipelined GEMM for propagation (cp.async double buffer) =====
// MODE 1 (BM=64): A = [relE | pEff[rr] | pEff[rs]] (K=384);
//                 epi = relu(+bias) -> atomicAdd bf16x2 into aggH[rr].
// MODE 2 (BM=32): A = [pEnc | aggH] (K=256);
//                 epi = relu(acc+bias+C[row]) -> C; re-zero aggH rows.
template <int MODE, int BM>
__global__ void __launch_bounds__(256) gemm2_k(
    const __nv_bfloat16* __restrict__ A,
    const __nv_bfloat16* __restrict__ G2,
    const __nv_bfloat16* __restrict__ W,
    const float* __restrict__ bias,
    __nv_bfloat16* __restrict__ C,
    __nv_bfloat16* __restrict__ aggH,
    const int* __restrict__ rr, const int* __restrict__ rs, int K)
{
    constexpr int WROWS = BM / 16;           // 4 or 2
    constexpr int NFR   = 128 / ((8 / WROWS) * 16);  // 4 or 2
    constexpr int SPAN  = NFR * 16;          // 64 or 32

    __shared__ union {
        struct {
            __nv_bfloat16 As[2][BM * 24];
            __nv_bfloat16 Ws[2][16 * 136];
        } s;
        float Cs[BM * 132];
    } u;
    __shared__ int   idxs[2 * BM > 128 ? 2 * BM : 128];
    __shared__ float biasm[128];

    int tid = threadIdx.x, wid = tid >> 5;
    int wm = wid % WROWS, wn = wid / WROWS;
    int rowBase = blockIdx.x * BM;

    if (MODE == 1) {
        if (tid < BM)          idxs[tid] = rr[rowBase + tid];
        else if (tid < 2 * BM) idxs[tid] = rs[rowBase + tid - BM];
    }
    if (tid < 128) biasm[tid] = bias[tid];

    int arow, acol;
    if (BM == 64) { arow = tid >> 2; acol = (tid & 3) * 4; }
    else          { arow = tid >> 3; acol = (tid & 7) * 2; }
    int wrow = tid >> 4, wcol = (tid & 15) * 8;

    uint32_t asB = (uint32_t)__cvta_generic_to_shared(&u.s.As[0][0]);
    uint32_t wsB = (uint32_t)__cvta_generic_to_shared(&u.s.Ws[0][0]);

    auto stage = [&](int kt, int buf) {
        int kg = kt * 16 + acol;
        const __nv_bfloat16* src;
        if (MODE == 1) {
            if (kg < 128)      src = A  + (size_t)(rowBase + arow) * 128 + kg;
            else if (kg < 256) src = G2 + (size_t)idxs[arow] * 128 + (kg - 128);
            else               src = G2 + (size_t)idxs[BM + arow] * 128 + (kg - 256);
        } else {
            if (kg < 128) src = A  + (size_t)(rowBase + arow) * 128 + kg;
            else          src = G2 + (size_t)(rowBase + arow) * 128 + (kg - 128);
        }
        uint32_t ad = asB + (uint32_t)(buf * BM * 24 + arow * 24 + acol) * 2;
        if (BM == 64) cpa8(ad, src); else cpa4(ad, src);
        uint32_t wd = wsB + (uint32_t)(buf * 16 * 136 + wrow * 136 + wcol) * 2;
        cpa16(wd, W + (size_t)(kt * 16 + wrow) * 128 + wcol);
    };

    wmma::fragment<wmma::accumulator, 16, 16, 16, float> acc[NFR];
#pragma unroll
    for (int nf = 0; nf < NFR; nf++) wmma::fill_fragment(acc[nf], 0.f);

    int kT = K / 16;
    stage(0, 0); cp_commit();
    for (int kt = 0; kt < kT; kt++) {
        if (kt + 1 < kT) { stage(kt + 1, (kt + 1) & 1); cp_commit(); cp_wait1(); }
        else             { cp_wait0(); }
        __syncthreads();
        int buf = kt & 1;
        wmma::fragment<wmma::matrix_a, 16, 16, 16, __nv_bfloat16, wmma::row_major> af;
        wmma::load_matrix_sync(af, &u.s.As[buf][wm * 16 * 24], 24);
#pragma unroll
        for (int nf = 0; nf < NFR; nf++) {
            wmma::fragment<wmma::matrix_b, 16, 16, 16, __nv_bfloat16, wmma::row_major> bf;
            wmma::load_matrix_sync(bf, &u.s.Ws[buf][wn * SPAN + nf * 16], 136);
            wmma::mma_sync(acc[nf], af, bf, acc[nf]);
        }
        __syncthreads();
    }

    // epilogue: stage accumulators (union overwrite is safe post-loop)
#pragma unroll
    for (int nf = 0; nf < NFR; nf++)
        wmma::store_matrix_sync(&u.Cs[(wm * 16) * 132 + wn * SPAN + nf * 16],
                                acc[nf], 132, wmma::mem_row_major);
    __syncthreads();
#pragma unroll
    for (int it = 0; it < BM / 8; it++) {
        int e = tid + it * 256, row = e >> 5, c4 = (e & 31) * 4;
        float4 v = *(float4*)&u.Cs[row * 132 + c4];
        float4 b = *(const float4*)&biasm[c4];
        if (MODE == 1) {
            __nv_bfloat162* dst =
                (__nv_bfloat162*)(aggH + (size_t)idxs[row] * 128 + c4);
            atomicAdd(dst,     __floats2bfloat162_rn(fmaxf(v.x + b.x, 0.f),
                                                     fmaxf(v.y + b.y, 0.f)));
            atomicAdd(dst + 1, __floats2bfloat162_rn(fmaxf(v.z + b.z, 0.f),
                                                     fmaxf(v.w + b.w, 0.f)));
        } else {
            size_t go = (size_t)(rowBase + row) * 128 + c4;
            uint2 rv = *(const uint2*)&C[go];
            float2 r0 = unpack_bf2(rv.x), r1 = unpack_bf2(rv.y);
            v.x = fmaxf(v.x + b.x + r0.x, 0.f);
            v.y = fmaxf(v.y + b.y + r0.y, 0.f);
            v.z = fmaxf(v.z + b.z + r1.x, 0.f);
            v.w = fmaxf(v.w + b.w + r1.y, 0.f);
            uint2 o; o.x = pack_bf2(v.x, v.y); o.y = pack_bf2(v.z, v.w);
            *(uint2*)&C[go] = o;
            *(uint2*)&aggH[go] = make_uint2(0u, 0u);   // re-zero for next step
        }
    }
}

// =====================  fused head: np0 + np1 + np2 + clamp + add ===========
#define HD_BIAS_OFF (256*136*2)                    // 69632
#define HD_W2_OFF   (HD_BIAS_OFF + 2*128*4)        // 70656
#define HD_B2_OFF   (HD_W2_OFF + 384*4)            // 72192
#define HD_ACT_OFF  (HD_B2_OFF + 16)               // 72208
#define HD_CS_OFF   (HD_ACT_OFF + 64*136*2)        // 89616
#define HD_SMEM     (HD_CS_OFF + 64*132*4)         // 123408

__global__ void __launch_bounds__(256) head_k(
    const __nv_bfloat16* __restrict__ pEff,
    const __nv_bfloat16* __restrict__ W0, const __nv_bfloat16* __restrict__ W1,
    const float* __restrict__ b0, const float* __restrict__ b1,
    const float* __restrict__ W2, const float* __restrict__ b2,
    const float* __restrict__ state, float* __restrict__ out)
{
    extern __shared__ char smraw[];
    __nv_bfloat16* Wsm  = (__nv_bfloat16*)smraw;
    float* biasm        = (float*)(smraw + HD_BIAS_OFF);
    float* W2s          = (float*)(smraw + HD_W2_OFF);
    float* b2s          = (float*)(smraw + HD_B2_OFF);
    __nv_bfloat16* Act  = (__nv_bfloat16*)(smraw + HD_ACT_OFF);
    float* Cs           = (float*)(smraw + HD_CS_OFF);
    int tid = threadIdx.x, wid = tid >> 5, lane = tid & 31;
    int wm = wid & 3, wn = wid >> 2;
    int rowBase = blockIdx.x * 64;

    for (int idx = tid; idx < 256 * 16; idx += 256) {
        int r = idx >> 4, c8 = (idx & 15) * 8;
        const __nv_bfloat16* src = (r < 128) ? W0 + (size_t)r * 128 + c8
                                             : W1 + (size_t)(r - 128) * 128 + c8;
        *(uint4*)&Wsm[r * 136 + c8] = *(const uint4*)src;
    }
    for (int i = tid; i < 128; i += 256) { biasm[i] = b0[i]; biasm[128 + i] = b1[i]; }
    for (int i = tid; i < 384; i += 256) W2s[i] = W2[i];
    if (tid < 3) b2s[tid] = b2[tid];
    for (int idx = tid; idx < 64 * 16; idx += 256) {
        int r = idx >> 4, c8 = (idx & 15) * 8;
        *(uint4*)&Act[r * 136 + c8] =
            *(const uint4*)(pEff + (size_t)(rowBase + r) * 128 + c8);
    }
    __syncthreads();

    for (int L = 0; L < 2; L++) {
        const __nv_bfloat16* WL = Wsm + (size_t)L * 128 * 136;
        wmma::fragment<wmma::accumulator, 16, 16, 16, float> acc[4];
#pragma unroll
        for (int nf = 0; nf < 4; nf++) wmma::fill_fragment(acc[nf], 0.f);
#pragma unroll
        for (int kc = 0; kc < 8; kc++) {
            wmma::fragment<wmma::matrix_a, 16, 16, 16, __nv_bfloat16, wmma::row_major> af;
            wmma::load_matrix_sync(af, Act + (wm * 16) * 136 + kc * 16, 136);
#pragma unroll
            for (int nf = 0; nf < 4; nf++) {
                wmma::fragment<wmma::matrix_b, 16, 16, 16, __nv_bfloat16, wmma::row_major> bf;
                wmma::load_matrix_sync(bf, WL + (kc * 16) * 136 + wn * 64 + nf * 16, 136);
                wmma::mma_sync(acc[nf], af, bf, acc[nf]);
            }
        }
#pragma unroll
        for (int nf = 0; nf < 4; nf++)
            wmma::store_matrix_sync(Cs + (wm * 16) * 132 + wn * 64 + nf * 16,
                                    acc[nf], 132, wmma::mem_row_major);
        __syncthreads();
        const float* bL = biasm + L * 128;
#pragma unroll
        for (int it = 0; it < 8; it++) {
            int e = tid + it * 256, row = e >> 5, c4 = (e & 31) * 4;
            float4 v = *(float4*)&Cs[row * 132 + c4];
            float4 b = *(const float4*)&bL[c4];
            uint2 o;
            o.x = pack_bf2(fmaxf(v.x + b.x, 0.f), fmaxf(v.y + b.y, 0.f));
            o.y = pack_bf2(fmaxf(v.z + b.z, 0.f), fmaxf(v.w + b.w, 0.f));
            *(uint2*)&Act[row * 136 + c4] = o;
        }
        __syncthreads();
    }

    // final 128->3, clamp, add last position
#pragma unroll
    for (int i = 0; i < 8; i++) {
        int row = wid * 8 + i;
        int grow = rowBase + row;
        int b = grow >> 11, n = grow & (NN - 1);
        float hv[4];
#pragma unroll
        for (int j = 0; j < 4; j++)
            hv[j] = __bfloat162float(Act[row * 136 + lane + 32 * j]);
#pragma unroll
        for (int k = 0; k < 3; k++) {
            float sacc = 0.f;
#pragma unroll
            for (int j = 0; j < 4; j++)
                sacc += hv[j] * W2s[(lane + 32 * j) * 3 + k];
#pragma unroll
            for (int off = 16; off; off >>= 1)
                sacc += __shfl_xor_sync(0xffffffffu, sacc, off);
            if (lane == 0 && n < NP) {
                float m = fminf(fmaxf(sacc + b2s[k], -100.f), 100.f);
                out[((size_t)b * NP + n) * 3 + k] =
                    state[((size_t)(b * 4 + 3) * NN + n) * 3 + k] + m;
            }
        }
    }
}

// ---------------------------------------------------------------------------
extern "C" void kernel_launch(void* const* d_in, const int* in_sizes, int n_in,
                              void* d_out, int out_size) {
    const float* state  = (const float*)d_in[0];
    const float* attrs  = (const float*)d_in[1];
    const float* Rr     = (const float*)d_in[2];
    const float* Rs     = (const float*)d_in[3];
    const float* pinst  = (const float*)d_in[4];
    const float* action = (const float*)d_in[5];
    const float* pden   = (const float*)d_in[6];
    const float* phys   = (const float*)d_in[7];
    const float* pe_W0 = (const float*)d_in[8],  *pe_b0 = (const float*)d_in[9];
    const float* pe_W1 = (const float*)d_in[10], *pe_b1 = (const float*)d_in[11];
    const float* pe_W2 = (const float*)d_in[12], *pe_b2 = (const float*)d_in[13];
    const float* re_W0 = (const float*)d_in[14], *re_b0 = (const float*)d_in[15];
    const float* re_W1 = (const float*)d_in[16], *re_b1 = (const float*)d_in[17];
    const float* re_W2 = (const float*)d_in[18], *re_b2 = (const float*)d_in[19];
    const float* pp_W  = (const float*)d_in[20], *pp_b  = (const float*)d_in[21];
    const float* rp_W  = (const float*)d_in[22], *rp_b  = (const float*)d_in[23];
    const float* np_W0 = (const float*)d_in[24], *np_b0 = (const float*)d_in[25];
    const float* np_W1 = (const float*)d_in[26], *np_b1 = (const float*)d_in[27];
    const float* np_W2 = (const float*)d_in[28], *np_b2 = (const float*)d_in[29];
    float* out = (float*)d_out;

    float *pin_f;
    __nv_bfloat16 *pin_h, *rin_h, *pEnc, *pEff, *relE, *aggH, *wbuf;
    int *rr, *rs;
    cudaGetSymbolAddress((void**)&pin_f, g_pin_f);
    cudaGetSymbolAddress((void**)&pin_h, g_pin_h);
    cudaGetSymbolAddress((void**)&rin_h, g_rin_h);
    cudaGetSymbolAddress((void**)&pEnc,  g_pEnc);
    cudaGetSymbolAddress((void**)&pEff,  g_pEff);
    cudaGetSymbolAddress((void**)&relE,  g_relE);
    cudaGetSymbolAddress((void**)&aggH,  g_aggH);
    cudaGetSymbolAddress((void**)&rr,    g_rr);
    cudaGetSymbolAddress((void**)&rs,    g_rs);
    cudaGetSymbolAddress((void**)&wbuf,  g_wbuf);

    cudaFuncSetAttribute(encmlp_k, cudaFuncAttributeMaxDynamicSharedMemorySize, ENC_SMEM);
    cudaFuncSetAttribute(head_k,   cudaFuncAttributeMaxDynamicSharedMemorySize, HD_SMEM);

    // 0) weights -> bf16
    WConvArgs wa;
    const float* srcs[10] = {pe_W0, pe_W1, pe_W2, re_W0, re_W1, re_W2,
                             pp_W, rp_W, np_W0, np_W1};
    const int starts[10]  = {WO_PE0, WO_PE1, WO_PE2, WO_RE0, WO_RE1, WO_RE2,
                             WO_PP, WO_RP, WO_NP0, WO_NP1};
    const int srows[10]   = {19, 128, 128, 56, 128, 128, 256, 384, 128, 128};
    for (int i = 0; i < 10; i++) {
        wa.src[i] = srcs[i]; wa.rowStart[i] = starts[i]; wa.srcRows[i] = srows[i];
    }
    convert_w<<<W_TOTAL_ROWS, 128>>>(wa, wbuf);

    // 1) edge indices
    extract_idx<<<(2 * BNR * 32 + 255) / 256, 256>>>(Rr, Rs, rr, rs);

    // 2) feature assembly
    build_pin<<<(NODES + 255) / 256, 256>>>(state, attrs, action, pden, phys,
                                            pin_f, pin_h);
    build_rin<<<(BNR * 64) / 256, 256>>>(pin_f, attrs, pinst, rr, rs, rin_h);

    // 3) fused 3-layer encoders (particle segment dups pEff + zeroes aggH)
    EncSeg sp, sr;
    sp.A = pin_h; sp.K0 = 32;
    sp.W0 = wbuf + WO_PE0 * 128; sp.W1 = wbuf + WO_PE1 * 128; sp.W2 = wbuf + WO_PE2 * 128;
    sp.b0 = pe_b0; sp.b1 = pe_b1; sp.b2 = pe_b2;
    sp.C = pEnc; sp.C2 = pEff; sp.aggz = aggH;
    sr.A = rin_h; sr.K0 = 64;
    sr.W0 = wbuf + WO_RE0 * 128; sr.W1 = wbuf + WO_RE1 * 128; sr.W2 = wbuf + WO_RE2 * 128;
    sr.b0 = re_b0; sr.b1 = re_b1; sr.b2 = re_b2;
    sr.C = relE; sr.C2 = nullptr; sr.aggz = nullptr;
    encmlp_k<<<NODES / 64 + BNR / 64, 256, ENC_SMEM>>>(sp, sr, NODES / 64);

    // 4) propagation: 3 steps, pipelined GEMMs
    for (int step = 0; step < 3; step++) {
        gemm2_k<1, 64><<<BNR / 64, 256>>>(relE, pEff, wbuf + WO_RP * 128, rp_b,
                                          nullptr, aggH, rr, rs, 384);
        gemm2_k<2, 32><<<NODES / 32, 256>>>(pEnc, aggH, wbuf + WO_PP * 128, pp_b,
                                            pEff, aggH, nullptr, nullptr, 256);
    }

    // 5) fused head
    head_k<<<NODES / 64, 256, HD_SMEM>>>(pEff, wbuf + WO_NP0 * 128,
                                         wbuf + WO_NP1 * 128, np_b0, np_b1,
                                         np_W2, np_b2, state, out);
}